// round 16
// baseline (speedup 1.0000x reference)
#include <cuda_runtime.h>
#include <cuda_fp16.h>

// ---------------------------------------------------------------------------
// GNNEncoder: 2-layer GCN. out[d] = dinv[d]*sum_{(s,d)}(x[s]@W)*dinv[s] + b
// R16 (fixes R15's host-side __device__-symbol bug: g_w1h/g_w1l were passed
//      as kernel args from host code -> garbage pointers. W arrays are now
//      selected INSIDE the kernel via the LAYER template param.)
//   - gemm1 stores UNSCALED fp16(x@W1) (no dinv dep) + fused edge histogram
//   - agg1 applies dinv[src] per edge + dinv[node] self loop (R7 body)
//   - W1/W2 hi/lo fp16 split precomputed once (W staging = pure copy)
//   - gemm2 (after scan) scales by dinv in epilogue; agg2 plain sum
// Pipeline: [wsplit, gemm1+hist, scan, fill, agg1, gemm2, agg2]
// All scratch in __device__ globals; graph-capturable (kernel launches only).
// ---------------------------------------------------------------------------

#define NODES_MAX 50000
#define EDGES_MAX 800000

__device__ int    g_cnt[NODES_MAX];          // self-cleaning (zeroed by scan)
__device__ int    g_off[NODES_MAX + 1];
__device__ int    g_cursor[NODES_MAX];
__device__ int    g_csr_src[EDGES_MAX];
__device__ float  g_dinv[NODES_MAX];
__device__ __half g_hs [NODES_MAX * 128];    // layer1 x@W1 (UNSCALED, gathered)
__device__ float  g_x2 [NODES_MAX * 128];    // layer1 output (post relu)
__device__ __half g_hs2[NODES_MAX * 64];     // layer2 (x2@W2)*dinv (gathered)
__device__ __half g_w1h[128 * 128];          // W1 hi/lo fp16 (precomputed)
__device__ __half g_w1l[128 * 128];
__device__ __half g_w2h[128 * 64];
__device__ __half g_w2l[128 * 64];

// ---- helpers ----------------------------------------------------------------
__device__ __forceinline__ unsigned sptr(const void* p)
{
    return (unsigned)__cvta_generic_to_shared(p);
}

__device__ __forceinline__ void ldm_x4(unsigned addr, unsigned& r0, unsigned& r1,
                                       unsigned& r2, unsigned& r3)
{
    asm volatile("ldmatrix.sync.aligned.m8n8.x4.shared.b16 {%0,%1,%2,%3}, [%4];"
                 : "=r"(r0), "=r"(r1), "=r"(r2), "=r"(r3) : "r"(addr));
}

__device__ __forceinline__ void ldm_x4t(unsigned addr, unsigned& r0, unsigned& r1,
                                        unsigned& r2, unsigned& r3)
{
    asm volatile("ldmatrix.sync.aligned.m8n8.x4.trans.shared.b16 {%0,%1,%2,%3}, [%4];"
                 : "=r"(r0), "=r"(r1), "=r"(r2), "=r"(r3) : "r"(addr));
}

__device__ __forceinline__ void mma16816(float* d, const unsigned* a,
                                         unsigned b0, unsigned b1)
{
    asm volatile(
        "mma.sync.aligned.m16n8k16.row.col.f32.f16.f16.f32 "
        "{%0,%1,%2,%3}, {%4,%5,%6,%7}, {%8,%9}, {%0,%1,%2,%3};"
        : "+f"(d[0]), "+f"(d[1]), "+f"(d[2]), "+f"(d[3])
        : "r"(a[0]), "r"(a[1]), "r"(a[2]), "r"(a[3]), "r"(b0), "r"(b1));
}

// split a float4 into hi/lo half2 pairs (x = h + l exactly to ~2^-22)
__device__ __forceinline__ void split4(float4 v, uint2& hi, uint2& lo)
{
    __half hx = __float2half_rn(v.x), hy = __float2half_rn(v.y);
    __half hz = __float2half_rn(v.z), hw = __float2half_rn(v.w);
    __half lx = __float2half_rn(v.x - __half2float(hx));
    __half ly = __float2half_rn(v.y - __half2float(hy));
    __half lz = __float2half_rn(v.z - __half2float(hz));
    __half lw = __float2half_rn(v.w - __half2float(hw));
    __half2 h01 = __halves2half2(hx, hy), h23 = __halves2half2(hz, hw);
    __half2 l01 = __halves2half2(lx, ly), l23 = __halves2half2(lz, lw);
    hi.x = *(unsigned*)&h01; hi.y = *(unsigned*)&h23;
    lo.x = *(unsigned*)&l01; lo.y = *(unsigned*)&l23;
}

// dtype detect: int64 viewed as int32 pairs -> odd words all zero.
__device__ __forceinline__ bool is_int32(const int* __restrict__ v)
{
    return (v[1] | v[3] | v[5] | v[7]) != 0;
}

// ---- W split precompute (once per launch; 6144 float4 slots) ---------------
__global__ void k_wsplit(const float* __restrict__ W1,
                         const float* __restrict__ W2)
{
    int t = blockIdx.x * blockDim.x + threadIdx.x;
    if (t < 4096) {                              // W1: 16384 floats / 4
        float4 w = ((const float4*)W1)[t];
        uint2 hi, lo;
        split4(w, hi, lo);
        ((uint2*)g_w1h)[t] = hi;
        ((uint2*)g_w1l)[t] = lo;
    } else if (t < 6144) {                       // W2: 8192 floats / 4
        int u = t - 4096;
        float4 w = ((const float4*)W2)[u];
        uint2 hi, lo;
        split4(w, hi, lo);
        ((uint2*)g_w2h)[u] = hi;
        ((uint2*)g_w2l)[u] = lo;
    }
}

// Single-block coalesced block-scan; zeroes g_cnt after reading (self-clean).
__global__ void __launch_bounds__(1024) k_scan1(int N, int E)
{
    __shared__ int wsum[32];
    __shared__ int stot;
    int t    = threadIdx.x;
    int lane = t & 31;
    int wid  = t >> 5;
    int carry = 0;
    int ntiles = (N + 1023) >> 10;

    for (int tile = 0; tile < ntiles; tile++) {
        int i = (tile << 10) + t;
        int c = 0;
        if (i < N) {
            c = g_cnt[i];
            g_cnt[i] = 0;                    // self-clean for next launch
        }
        int incl = c;
#pragma unroll
        for (int o = 1; o < 32; o <<= 1) {
            int vv = __shfl_up_sync(0xffffffffu, incl, o);
            if (lane >= o) incl += vv;
        }
        if (lane == 31) wsum[wid] = incl;
        __syncthreads();
        if (wid == 0) {
            int s  = wsum[lane];
            int si = s;
#pragma unroll
            for (int o = 1; o < 32; o <<= 1) {
                int vv = __shfl_up_sync(0xffffffffu, si, o);
                if (lane >= o) si += vv;
            }
            wsum[lane] = si - s;
            if (lane == 31) stot = si;
        }
        __syncthreads();
        int off = carry + wsum[wid] + incl - c;
        if (i < N) {
            g_off[i]    = off;
            g_cursor[i] = off;
            g_dinv[i]   = rsqrtf((float)(c + 1));   // +1 self loop
        }
        carry += stot;
        __syncthreads();
    }
    if (t == 0) g_off[N] = E;
}

__global__ void k_fill(const int* __restrict__ v, int E, int N)
{
    int base = (blockIdx.x * blockDim.x + threadIdx.x) * 4;
    if (base >= E) return;
    bool is32 = is_int32(v);
    if (base + 4 <= E) {
        unsigned s0, s1, s2, s3, d0, d1, d2, d3;
        if (is32) {
            int4 a = *(const int4*)&v[base];
            int4 b = *(const int4*)&v[E + base];
            s0 = a.x; s1 = a.y; s2 = a.z; s3 = a.w;
            d0 = b.x; d1 = b.y; d2 = b.z; d3 = b.w;
        } else {
            int4 a = *(const int4*)&v[2 * base];
            int4 b = *(const int4*)&v[2 * base + 4];
            int4 c = *(const int4*)&v[2 * E + 2 * base];
            int4 d = *(const int4*)&v[2 * E + 2 * base + 4];
            s0 = a.x; s1 = a.z; s2 = b.x; s3 = b.z;
            d0 = c.x; d1 = c.z; d2 = d.x; d3 = d.z;
        }
        if (d0 < (unsigned)N && s0 < (unsigned)N)
            g_csr_src[atomicAdd(&g_cursor[d0], 1)] = (int)s0;
        if (d1 < (unsigned)N && s1 < (unsigned)N)
            g_csr_src[atomicAdd(&g_cursor[d1], 1)] = (int)s1;
        if (d2 < (unsigned)N && s2 < (unsigned)N)
            g_csr_src[atomicAdd(&g_cursor[d2], 1)] = (int)s2;
        if (d3 < (unsigned)N && s3 < (unsigned)N)
            g_csr_src[atomicAdd(&g_cursor[d3], 1)] = (int)s3;
    } else {
        int st = is32 ? 1 : 2, dbase = is32 ? E : 2 * E;
        for (int i = base; i < E; i++) {
            unsigned d  = (unsigned)v[dbase + st * i];
            unsigned sr = (unsigned)v[st * i];
            if (d < (unsigned)N && sr < (unsigned)N)
                g_csr_src[atomicAdd(&g_cursor[d], 1)] = (int)sr;
        }
    }
}

// ---------------------------------------------------------------------------
// Tensor-core GEMM (2-term split; W h/l selected INSIDE kernel by LAYER):
//   LAYER 0: g_hs  = fp16(X@W1)          (UNSCALED) + fused edge histogram
//   LAYER 1: g_hs2 = fp16((x2@W2)*dinv)
// ---------------------------------------------------------------------------
template <int DOUT, int LAYER>
__global__ void __launch_bounds__(256, 3)
k_gemm(const float* __restrict__ Xp, int N,
       const int* __restrict__ ev, int E)
{
    constexpr int BK  = 32;
    constexpr int WC  = DOUT / 32;     // warp-cols (4 or 2)
    constexpr int WR  = 8 / WC;        // warp-rows (2 or 4)
    constexpr int BM  = WR * 32;       // block rows (64 or 128)
    constexpr int SXH = BK + 8;        // xs half-stride (40)
    constexpr int SWH = DOUT + 8;      // ws half-stride (136/72)

    const float*  X  = (LAYER == 0) ? Xp : g_x2;
    __half*       H  = (LAYER == 0) ? g_hs : g_hs2;
    const __half* Wh = (LAYER == 0) ? g_w1h : g_w2h;   // device-side symbol ref
    const __half* Wl = (LAYER == 0) ? g_w1l : g_w2l;

    __shared__ __align__(16) __half xs_h[BM * SXH];
    __shared__ __align__(16) __half xs_l[BM * SXH];
    __shared__ __align__(16) __half ws_h[BK * SWH];
    __shared__ __align__(16) __half ws_l[BK * SWH];

    int t    = threadIdx.x;
    int w    = t >> 5;
    int lane = t & 31;
    int warpRow = w / WC;
    int warpCol = w % WC;
    int rowW0   = warpRow * 32;
    int colW0   = warpCol * 32;
    int row0    = blockIdx.x * BM;

    float acc[2][4][4];
#pragma unroll
    for (int mt = 0; mt < 2; mt++)
#pragma unroll
        for (int nt = 0; nt < 4; nt++)
#pragma unroll
            for (int q = 0; q < 4; q++) acc[mt][nt][q] = 0.f;

    int a_row = (lane & 15);
    int a_col = (lane >> 4) * 8;
    int b_row = ((lane >> 3) & 1) * 8 + (lane & 7);
    int b_col = (lane >> 4) * 8;

    for (int kk = 0; kk < 128; kk += BK) {
        // stage X chunk (split h/l — X is fp32)
#pragma unroll
        for (int u = 0; u < BM / 32; u++) {
            int idx = u * 256 + t;
            int r   = idx >> 3;
            int j4  = idx & 7;
            int row = row0 + r;
            float4 x = make_float4(0.f, 0.f, 0.f, 0.f);
            if (row < N) x = *(const float4*)&X[row * 128 + kk + j4 * 4];
            uint2 hi, lo;
            split4(x, hi, lo);
            *(uint2*)&xs_h[r * SXH + j4 * 4] = hi;
            *(uint2*)&xs_l[r * SXH + j4 * 4] = lo;
        }
        // stage W chunk: pure copy of precomputed fp16 (uint4 = 8 halves)
#pragma unroll
        for (int u = 0; u < DOUT / 64; u++) {
            int idx = u * 256 + t;                 // BK*DOUT/8 slots
            int k   = idx / (DOUT / 8);
            int c8  = (idx % (DOUT / 8)) * 8;
            *(uint4*)&ws_h[k * SWH + c8] = *(const uint4*)&Wh[(kk + k) * DOUT + c8];
            *(uint4*)&ws_l[k * SWH + c8] = *(const uint4*)&Wl[(kk + k) * DOUT + c8];
        }
        __syncthreads();

#pragma unroll
        for (int ks = 0; ks < BK; ks += 16) {
            unsigned ah[2][4], al[2][4];
#pragma unroll
            for (int mt = 0; mt < 2; mt++) {
                int r = rowW0 + mt * 16 + a_row;
                int c = ks + a_col;
                ldm_x4(sptr(&xs_h[r * SXH + c]), ah[mt][0], ah[mt][1], ah[mt][2], ah[mt][3]);
                ldm_x4(sptr(&xs_l[r * SXH + c]), al[mt][0], al[mt][1], al[mt][2], al[mt][3]);
            }
            unsigned bh[2][4], bl[2][4];
#pragma unroll
            for (int np = 0; np < 2; np++) {
                int k = ks + b_row;
                int n = colW0 + np * 16 + b_col;
                ldm_x4t(sptr(&ws_h[k * SWH + n]), bh[np][0], bh[np][1], bh[np][2], bh[np][3]);
                ldm_x4t(sptr(&ws_l[k * SWH + n]), bl[np][0], bl[np][1], bl[np][2], bl[np][3]);
            }
#pragma unroll
            for (int mt = 0; mt < 2; mt++) {
#pragma unroll
                for (int nt = 0; nt < 4; nt++) {
                    int np = nt >> 1, hf = (nt & 1) * 2;
                    mma16816(acc[mt][nt], ah[mt], bh[np][hf], bh[np][hf + 1]);
                    mma16816(acc[mt][nt], ah[mt], bl[np][hf], bl[np][hf + 1]);
                    mma16816(acc[mt][nt], al[mt], bh[np][hf], bh[np][hf + 1]);
                }
            }
        }
        __syncthreads();
    }

    // epilogue: LAYER 0 stores raw; LAYER 1 scales by dinv.
#pragma unroll
    for (int mt = 0; mt < 2; mt++) {
#pragma unroll
        for (int nt = 0; nt < 4; nt++) {
            int col = colW0 + nt * 8 + (lane & 3) * 2;
            int r0  = row0 + rowW0 + mt * 16 + (lane >> 2);
            int r1  = r0 + 8;
            if (r0 < N) {
                float s = (LAYER == 0) ? 1.f : g_dinv[r0];
                __half2 h = __floats2half2_rn(acc[mt][nt][0] * s, acc[mt][nt][1] * s);
                *(unsigned*)&H[r0 * DOUT + col] = *(unsigned*)&h;
            }
            if (r1 < N) {
                float s = (LAYER == 0) ? 1.f : g_dinv[r1];
                __half2 h = __floats2half2_rn(acc[mt][nt][2] * s, acc[mt][nt][3] * s);
                *(unsigned*)&H[r1 * DOUT + col] = *(unsigned*)&h;
            }
        }
    }

    // ---- fused edge histogram (LAYER 0 only): this block's edge slice ------
    if (LAYER == 0) {
        int nblk = gridDim.x;
        int epb  = (E + nblk - 1) / nblk;          // edges per block
        int eb   = blockIdx.x * epb;
        int ee   = min(eb + epb, E);
        bool is32 = is_int32(ev);
        for (int base = eb + t * 4; base < ee; base += 256 * 4) {
            int lim = min(4, ee - base);
            if (is32) {
                if (lim == 4) {
                    int4 a = *(const int4*)&ev[E + base];
                    unsigned d0 = a.x, d1 = a.y, d2 = a.z, d3 = a.w;
                    if (d0 < (unsigned)N) atomicAdd(&g_cnt[d0], 1);
                    if (d1 < (unsigned)N) atomicAdd(&g_cnt[d1], 1);
                    if (d2 < (unsigned)N) atomicAdd(&g_cnt[d2], 1);
                    if (d3 < (unsigned)N) atomicAdd(&g_cnt[d3], 1);
                } else {
                    for (int j = 0; j < lim; j++) {
                        unsigned d = (unsigned)ev[E + base + j];
                        if (d < (unsigned)N) atomicAdd(&g_cnt[d], 1);
                    }
                }
            } else {
                if (lim == 4) {
                    int4 a = *(const int4*)&ev[2 * E + 2 * base];
                    int4 b = *(const int4*)&ev[2 * E + 2 * base + 4];
                    unsigned d0 = a.x, d1 = a.z, d2 = b.x, d3 = b.z;
                    if (d0 < (unsigned)N) atomicAdd(&g_cnt[d0], 1);
                    if (d1 < (unsigned)N) atomicAdd(&g_cnt[d1], 1);
                    if (d2 < (unsigned)N) atomicAdd(&g_cnt[d2], 1);
                    if (d3 < (unsigned)N) atomicAdd(&g_cnt[d3], 1);
                } else {
                    for (int j = 0; j < lim; j++) {
                        unsigned d = (unsigned)ev[2 * E + 2 * (base + j)];
                        if (d < (unsigned)N) atomicAdd(&g_cnt[d], 1);
                    }
                }
            }
        }
    }
}

// ---------------------------------------------------------------------------
// Layer-1 aggregate (dinv-weighted; hs is UNSCALED):
//   x2[d] = relu(dinv[d]*(hs[d]*dinv[d] + sum_in hs[src]*dinv[src]) + b1)
// ---------------------------------------------------------------------------
__global__ void k_agg1(const float* __restrict__ bias, int N)
{
    constexpr int DOUT = 128;
    constexpr int TPN  = DOUT / 8;        // 16 threads per node
    constexpr int NPB  = 256 / TPN;       // 16 nodes per block

    int t    = threadIdx.x;
    int node = blockIdx.x * NPB + t / TPN;
    int c8   = (t % TPN) * 8;
    if (node >= N) return;

    float dnode = g_dinv[node];
    float a[8];
    {   // self loop: hs[d]*dinv[d]
        uint4 v = *(const uint4*)&g_hs[node * DOUT + c8];
        float2 f0 = __half22float2(*(__half2*)&v.x);
        float2 f1 = __half22float2(*(__half2*)&v.y);
        float2 f2 = __half22float2(*(__half2*)&v.z);
        float2 f3 = __half22float2(*(__half2*)&v.w);
        a[0] = f0.x * dnode; a[1] = f0.y * dnode;
        a[2] = f1.x * dnode; a[3] = f1.y * dnode;
        a[4] = f2.x * dnode; a[5] = f2.y * dnode;
        a[6] = f3.x * dnode; a[7] = f3.y * dnode;
    }

    int i = g_off[node];
    int e = g_off[node + 1];
    for (; i + 4 <= e; i += 4) {
        int s0 = g_csr_src[i + 0];
        int s1 = g_csr_src[i + 1];
        int s2 = g_csr_src[i + 2];
        int s3 = g_csr_src[i + 3];
        uint4 v0 = *(const uint4*)&g_hs[s0 * DOUT + c8];
        uint4 v1 = *(const uint4*)&g_hs[s1 * DOUT + c8];
        uint4 v2 = *(const uint4*)&g_hs[s2 * DOUT + c8];
        uint4 v3 = *(const uint4*)&g_hs[s3 * DOUT + c8];
        float dv0 = g_dinv[s0];
        float dv1 = g_dinv[s1];
        float dv2 = g_dinv[s2];
        float dv3 = g_dinv[s3];
#pragma unroll
        for (int q = 0; q < 4; q++) {
            unsigned w0 = (&v0.x)[q], w1 = (&v1.x)[q],
                     w2 = (&v2.x)[q], w3 = (&v3.x)[q];
            float2 f0 = __half22float2(*(__half2*)&w0);
            float2 f1 = __half22float2(*(__half2*)&w1);
            float2 f2 = __half22float2(*(__half2*)&w2);
            float2 f3 = __half22float2(*(__half2*)&w3);
            a[2 * q]     = fmaf(f0.x, dv0, a[2 * q]);
            a[2 * q]     = fmaf(f1.x, dv1, a[2 * q]);
            a[2 * q]     = fmaf(f2.x, dv2, a[2 * q]);
            a[2 * q]     = fmaf(f3.x, dv3, a[2 * q]);
            a[2 * q + 1] = fmaf(f0.y, dv0, a[2 * q + 1]);
            a[2 * q + 1] = fmaf(f1.y, dv1, a[2 * q + 1]);
            a[2 * q + 1] = fmaf(f2.y, dv2, a[2 * q + 1]);
            a[2 * q + 1] = fmaf(f3.y, dv3, a[2 * q + 1]);
        }
    }
    for (; i < e; i++) {
        int s0 = g_csr_src[i];
        uint4 v = *(const uint4*)&g_hs[s0 * DOUT + c8];
        float dv = g_dinv[s0];
#pragma unroll
        for (int q = 0; q < 4; q++) {
            unsigned w0 = (&v.x)[q];
            float2 f = __half22float2(*(__half2*)&w0);
            a[2 * q]     = fmaf(f.x, dv, a[2 * q]);
            a[2 * q + 1] = fmaf(f.y, dv, a[2 * q + 1]);
        }
    }

    float r[8];
#pragma unroll
    for (int q = 0; q < 8; q++)
        r[q] = fmaxf(a[q] * dnode + bias[c8 + q], 0.f);
    float4 ob0 = make_float4(r[0], r[1], r[2], r[3]);
    float4 ob1 = make_float4(r[4], r[5], r[6], r[7]);
    *(float4*)&g_x2[node * DOUT + c8]     = ob0;
    *(float4*)&g_x2[node * DOUT + c8 + 4] = ob1;
}

// ---------------------------------------------------------------------------
// Layer-2 aggregate: out[d] = dinv[d]*(hs2[d] + sum_in hs2[src]) + b2
// (hs2 already dinv-scaled)
// ---------------------------------------------------------------------------
__global__ void k_agg2(const float* __restrict__ bias,
                       float* __restrict__ outp, int N)
{
    constexpr int DOUT = 64;
    constexpr int TPN  = DOUT / 8;        // 8 threads per node
    constexpr int NPB  = 256 / TPN;       // 32 nodes per block

    int t    = threadIdx.x;
    int node = blockIdx.x * NPB + t / TPN;
    int c8   = (t % TPN) * 8;
    if (node >= N) return;

    float a[8];
    {
        uint4 v = *(const uint4*)&g_hs2[node * DOUT + c8];
        float2 f0 = __half22float2(*(__half2*)&v.x);
        float2 f1 = __half22float2(*(__half2*)&v.y);
        float2 f2 = __half22float2(*(__half2*)&v.z);
        float2 f3 = __half22float2(*(__half2*)&v.w);
        a[0] = f0.x; a[1] = f0.y; a[2] = f1.x; a[3] = f1.y;
        a[4] = f2.x; a[5] = f2.y; a[6] = f3.x; a[7] = f3.y;
    }

    int i = g_off[node];
    int e = g_off[node + 1];
    for (; i + 4 <= e; i += 4) {
        int s0 = g_csr_src[i + 0];
        int s1 = g_csr_src[i + 1];
        int s2 = g_csr_src[i + 2];
        int s3 = g_csr_src[i + 3];
        uint4 v0 = *(const uint4*)&g_hs2[s0 * DOUT + c8];
        uint4 v1 = *(const uint4*)&g_hs2[s1 * DOUT + c8];
        uint4 v2 = *(const uint4*)&g_hs2[s2 * DOUT + c8];
        uint4 v3 = *(const uint4*)&g_hs2[s3 * DOUT + c8];
#pragma unroll
        for (int q = 0; q < 4; q++) {
            unsigned w0 = (&v0.x)[q], w1 = (&v1.x)[q],
                     w2 = (&v2.x)[q], w3 = (&v3.x)[q];
            float2 f0 = __half22float2(*(__half2*)&w0);
            float2 f1 = __half22float2(*(__half2*)&w1);
            float2 f2 = __half22float2(*(__half2*)&w2);
            float2 f3 = __half22float2(*(__half2*)&w3);
            a[2 * q]     += f0.x + f1.x + f2.x + f3.x;
            a[2 * q + 1] += f0.y + f1.y + f2.y + f3.y;
        }
    }
    for (; i < e; i++) {
        int s0 = g_csr_src[i];
        uint4 v = *(const uint4*)&g_hs2[s0 * DOUT + c8];
#pragma unroll
        for (int q = 0; q < 4; q++) {
            unsigned w0 = (&v.x)[q];
            float2 f = __half22float2(*(__half2*)&w0);
            a[2 * q]     += f.x;
            a[2 * q + 1] += f.y;
        }
    }

    float d = g_dinv[node];
    float r[8];
#pragma unroll
    for (int q = 0; q < 8; q++)
        r[q] = a[q] * d + bias[c8 + q];
    float4 ob0 = make_float4(r[0], r[1], r[2], r[3]);
    float4 ob1 = make_float4(r[4], r[5], r[6], r[7]);
    *(float4*)&outp[node * DOUT + c8]     = ob0;
    *(float4*)&outp[node * DOUT + c8 + 4] = ob1;
}

// ---------------------------------------------------------------------------
extern "C" void kernel_launch(void* const* d_in, const int* in_sizes, int n_in,
                              void* d_out, int out_size)
{
    const float* e_prev = (const float*)d_in[0];
    const int*   ei     = (const int*)d_in[1];
    const float* W1     = (const float*)d_in[2];
    const float* b1     = (const float*)d_in[3];
    const float* W2     = (const float*)d_in[4];
    const float* b2     = (const float*)d_in[5];
    float*       out    = (float*)d_out;

    int N = in_sizes[0] / 128;   // 50000
    int E = in_sizes[1] / 2;     // 800000

    // W hi/lo split (once per call)
    k_wsplit<<<24, 256>>>(W1, W2);                            // #1

    // Layer 1 GEMM (UNSCALED output; no dinv dependency) + fused histogram
    k_gemm<128, 0><<<(N + 63) / 64, 256>>>(e_prev, N, ei, E); // #2

    // CSR build (scan computes dinv; self-cleans g_cnt)
    k_scan1<<<1, 1024>>>(N, E);                               // #3
    k_fill <<<(E / 4 + 255) / 256, 256>>>(ei, E, N);          // #4

    // Layer 1 aggregate (applies dinv per edge)
    k_agg1<<<(N + 15) / 16, 256>>>(b1, N);                    // #5

    // Layer 2 (dinv available)
    k_gemm<64, 1><<<(N + 127) / 128, 256>>>(nullptr, N, nullptr, 0); // #6
    k_agg2<<<(N + 31) / 32, 256>>>(b2, out, N);               // #7
}

// round 17
// speedup vs baseline: 1.0913x; 1.0913x over previous
#include <cuda_runtime.h>
#include <cuda_fp16.h>

// ---------------------------------------------------------------------------
// GNNEncoder: 2-layer GCN. out[d] = dinv[d]*sum_{(s,d)}(x[s]@W)*dinv[s] + b
// R17: exact R10 skeleton (best measured, 138.5us) with ONE change:
//   GEMM = 2-term  D = Xh*(Wh+Wl)  — W hi/lo precomputed in k_init (exactly
//   corrected weights), only X fp16 rounding remains (~1.4e-4 RMS/layer).
//   Removes all xs_l staging + 1/3 of mma -> attacks measured L1=55% bound.
// Pipeline (8 launches): [init+wsplit, hist, scan, fill, gemm1, agg1,
//                         gemm2, agg2]
// All scratch in __device__ globals; graph-capturable (kernel launches only).
// ---------------------------------------------------------------------------

#define NODES_MAX 50000
#define EDGES_MAX 800000

__device__ int    g_odd_or;                 // !=0 => edge_index is int32
__device__ int    g_cnt[NODES_MAX];
__device__ int    g_off[NODES_MAX + 1];
__device__ int    g_cursor[NODES_MAX];
__device__ int    g_csr_src[EDGES_MAX];
__device__ float  g_dinv[NODES_MAX];
__device__ __half g_hs [NODES_MAX * 128];   // layer1 (x@W1)*dinv  (gathered)
__device__ float  g_x2 [NODES_MAX * 128];   // layer1 output (post relu)
__device__ __half g_hs2[NODES_MAX * 64];    // layer2 (x2@W2)*dinv (gathered)
__device__ __half g_w1h[128 * 128];         // W hi/lo fp16 (precomputed)
__device__ __half g_w1l[128 * 128];
__device__ __half g_w2h[128 * 64];
__device__ __half g_w2l[128 * 64];

// ---- helpers ----------------------------------------------------------------
__device__ __forceinline__ unsigned sptr(const void* p)
{
    return (unsigned)__cvta_generic_to_shared(p);
}

__device__ __forceinline__ void ldm_x4(unsigned addr, unsigned& r0, unsigned& r1,
                                       unsigned& r2, unsigned& r3)
{
    asm volatile("ldmatrix.sync.aligned.m8n8.x4.shared.b16 {%0,%1,%2,%3}, [%4];"
                 : "=r"(r0), "=r"(r1), "=r"(r2), "=r"(r3) : "r"(addr));
}

__device__ __forceinline__ void ldm_x4t(unsigned addr, unsigned& r0, unsigned& r1,
                                        unsigned& r2, unsigned& r3)
{
    asm volatile("ldmatrix.sync.aligned.m8n8.x4.trans.shared.b16 {%0,%1,%2,%3}, [%4];"
                 : "=r"(r0), "=r"(r1), "=r"(r2), "=r"(r3) : "r"(addr));
}

__device__ __forceinline__ void mma16816(float* d, const unsigned* a,
                                         unsigned b0, unsigned b1)
{
    asm volatile(
        "mma.sync.aligned.m16n8k16.row.col.f32.f16.f16.f32 "
        "{%0,%1,%2,%3}, {%4,%5,%6,%7}, {%8,%9}, {%0,%1,%2,%3};"
        : "+f"(d[0]), "+f"(d[1]), "+f"(d[2]), "+f"(d[3])
        : "r"(a[0]), "r"(a[1]), "r"(a[2]), "r"(a[3]), "r"(b0), "r"(b1));
}

// split a float4 into hi/lo half2 pairs (w = h + l exactly to ~2^-22)
__device__ __forceinline__ void split4(float4 v, uint2& hi, uint2& lo)
{
    __half hx = __float2half_rn(v.x), hy = __float2half_rn(v.y);
    __half hz = __float2half_rn(v.z), hw = __float2half_rn(v.w);
    __half lx = __float2half_rn(v.x - __half2float(hx));
    __half ly = __float2half_rn(v.y - __half2float(hy));
    __half lz = __float2half_rn(v.z - __half2float(hz));
    __half lw = __float2half_rn(v.w - __half2float(hw));
    __half2 h01 = __halves2half2(hx, hy), h23 = __halves2half2(hz, hw);
    __half2 l01 = __halves2half2(lx, ly), l23 = __halves2half2(lz, lw);
    hi.x = *(unsigned*)&h01; hi.y = *(unsigned*)&h23;
    lo.x = *(unsigned*)&l01; lo.y = *(unsigned*)&l23;
}

// ---- CSR init + dtype detect + W hi/lo split --------------------------------
__global__ void k_init(const int* __restrict__ v,
                       const float* __restrict__ W1,
                       const float* __restrict__ W2, int N)
{
    int i = blockIdx.x * blockDim.x + threadIdx.x;
    if (i < N) g_cnt[i] = 0;
    if (i == 0) g_odd_or = 0;
    // dtype detect: int64 viewed as int32 pairs -> odd words all zero.
    if (i < 256 && v[2 * i + 1] != 0) atomicOr(&g_odd_or, 1);
    // W split (6144 float4 slots total)
    if (i < 4096) {                              // W1: 16384 floats / 4
        float4 w = ((const float4*)W1)[i];
        uint2 hi, lo;
        split4(w, hi, lo);
        ((uint2*)g_w1h)[i] = hi;
        ((uint2*)g_w1l)[i] = lo;
    } else if (i < 6144) {                       // W2: 8192 floats / 4
        int u = i - 4096;
        float4 w = ((const float4*)W2)[u];
        uint2 hi, lo;
        split4(w, hi, lo);
        ((uint2*)g_w2h)[u] = hi;
        ((uint2*)g_w2l)[u] = lo;
    }
}

__global__ void k_hist(const int* __restrict__ v, int E, int N)
{
    int base = (blockIdx.x * blockDim.x + threadIdx.x) * 4;
    if (base >= E) return;
    int is32 = g_odd_or;
    if (base + 4 <= E) {
        unsigned d0, d1, d2, d3;
        if (is32) {
            int4 a = *(const int4*)&v[E + base];
            d0 = a.x; d1 = a.y; d2 = a.z; d3 = a.w;
        } else {
            int4 a = *(const int4*)&v[2 * E + 2 * base];
            int4 b = *(const int4*)&v[2 * E + 2 * base + 4];
            d0 = a.x; d1 = a.z; d2 = b.x; d3 = b.z;
        }
        if (d0 < (unsigned)N) atomicAdd(&g_cnt[d0], 1);
        if (d1 < (unsigned)N) atomicAdd(&g_cnt[d1], 1);
        if (d2 < (unsigned)N) atomicAdd(&g_cnt[d2], 1);
        if (d3 < (unsigned)N) atomicAdd(&g_cnt[d3], 1);
    } else {
        int s = is32 ? 1 : 2, dbase = is32 ? E : 2 * E;
        for (int i = base; i < E; i++) {
            unsigned d = (unsigned)v[dbase + s * i];
            if (d < (unsigned)N) atomicAdd(&g_cnt[d], 1);
        }
    }
}

// Single-block coalesced block-scan (tiles of 1024, shfl + smem, carry).
__global__ void __launch_bounds__(1024) k_scan1(int N, int E)
{
    __shared__ int wsum[32];
    __shared__ int stot;
    int t    = threadIdx.x;
    int lane = t & 31;
    int wid  = t >> 5;
    int carry = 0;
    int ntiles = (N + 1023) >> 10;

    for (int tile = 0; tile < ntiles; tile++) {
        int i = (tile << 10) + t;
        int c = (i < N) ? g_cnt[i] : 0;
        int incl = c;
#pragma unroll
        for (int o = 1; o < 32; o <<= 1) {
            int vv = __shfl_up_sync(0xffffffffu, incl, o);
            if (lane >= o) incl += vv;
        }
        if (lane == 31) wsum[wid] = incl;
        __syncthreads();
        if (wid == 0) {
            int s  = wsum[lane];
            int si = s;
#pragma unroll
            for (int o = 1; o < 32; o <<= 1) {
                int vv = __shfl_up_sync(0xffffffffu, si, o);
                if (lane >= o) si += vv;
            }
            wsum[lane] = si - s;
            if (lane == 31) stot = si;
        }
        __syncthreads();
        int off = carry + wsum[wid] + incl - c;
        if (i < N) {
            g_off[i]    = off;
            g_cursor[i] = off;
            g_dinv[i]   = rsqrtf((float)(c + 1));
        }
        carry += stot;
        __syncthreads();
    }
    if (t == 0) g_off[N] = E;
}

__global__ void k_fill(const int* __restrict__ v, int E, int N)
{
    int base = (blockIdx.x * blockDim.x + threadIdx.x) * 4;
    if (base >= E) return;
    int is32 = g_odd_or;
    if (base + 4 <= E) {
        unsigned s0, s1, s2, s3, d0, d1, d2, d3;
        if (is32) {
            int4 a = *(const int4*)&v[base];
            int4 b = *(const int4*)&v[E + base];
            s0 = a.x; s1 = a.y; s2 = a.z; s3 = a.w;
            d0 = b.x; d1 = b.y; d2 = b.z; d3 = b.w;
        } else {
            int4 a = *(const int4*)&v[2 * base];
            int4 b = *(const int4*)&v[2 * base + 4];
            int4 c = *(const int4*)&v[2 * E + 2 * base];
            int4 d = *(const int4*)&v[2 * E + 2 * base + 4];
            s0 = a.x; s1 = a.z; s2 = b.x; s3 = b.z;
            d0 = c.x; d1 = c.z; d2 = d.x; d3 = d.z;
        }
        if (d0 < (unsigned)N && s0 < (unsigned)N)
            g_csr_src[atomicAdd(&g_cursor[d0], 1)] = (int)s0;
        if (d1 < (unsigned)N && s1 < (unsigned)N)
            g_csr_src[atomicAdd(&g_cursor[d1], 1)] = (int)s1;
        if (d2 < (unsigned)N && s2 < (unsigned)N)
            g_csr_src[atomicAdd(&g_cursor[d2], 1)] = (int)s2;
        if (d3 < (unsigned)N && s3 < (unsigned)N)
            g_csr_src[atomicAdd(&g_cursor[d3], 1)] = (int)s3;
    } else {
        int st = is32 ? 1 : 2, dbase = is32 ? E : 2 * E;
        for (int i = base; i < E; i++) {
            unsigned d  = (unsigned)v[dbase + st * i];
            unsigned sr = (unsigned)v[st * i];
            if (d < (unsigned)N && sr < (unsigned)N)
                g_csr_src[atomicAdd(&g_cursor[d], 1)] = (int)sr;
        }
    }
}

// ---------------------------------------------------------------------------
// Tensor-core GEMM, 2-term: D = Xh*(Wh+Wl)  (W exactly corrected; only X
// fp16 rounding remains). H16[row] = fp16(D * dinv[row]).
//   Block 256 = 8 warps; warp tile 32x32; BK=32; 2 mma per (mt,nt) step.
// ---------------------------------------------------------------------------
template <int DOUT, int LAYER>
__global__ void __launch_bounds__(256)
k_gemm(const float* __restrict__ Xp, int N)
{
    constexpr int BK  = 32;
    constexpr int WC  = DOUT / 32;     // warp-cols (4 or 2)
    constexpr int WR  = 8 / WC;        // warp-rows (2 or 4)
    constexpr int BM  = WR * 32;       // block rows (64 or 128)
    constexpr int SXH = BK + 8;        // xs stride (40)
    constexpr int SWH = DOUT + 8;      // ws stride (136/72)

    const float*  X  = (LAYER == 0) ? Xp : g_x2;
    __half*       H  = (LAYER == 0) ? g_hs : g_hs2;
    const __half* Wh = (LAYER == 0) ? g_w1h : g_w2h;
    const __half* Wl = (LAYER == 0) ? g_w1l : g_w2l;

    __shared__ __align__(16) __half xs  [BM * SXH];
    __shared__ __align__(16) __half ws_h[BK * SWH];
    __shared__ __align__(16) __half ws_l[BK * SWH];

    int t    = threadIdx.x;
    int w    = t >> 5;
    int lane = t & 31;
    int warpRow = w / WC;
    int warpCol = w % WC;
    int rowW0   = warpRow * 32;
    int colW0   = warpCol * 32;
    int row0    = blockIdx.x * BM;

    float acc[2][4][4];
#pragma unroll
    for (int mt = 0; mt < 2; mt++)
#pragma unroll
        for (int nt = 0; nt < 4; nt++)
#pragma unroll
            for (int q = 0; q < 4; q++) acc[mt][nt][q] = 0.f;

    int a_row = (lane & 15);
    int a_col = (lane >> 4) * 8;
    int b_row = ((lane >> 3) & 1) * 8 + (lane & 7);
    int b_col = (lane >> 4) * 8;

    for (int kk = 0; kk < 128; kk += BK) {
        // stage X chunk: plain fp16 round (no split)
#pragma unroll
        for (int u = 0; u < BM / 32; u++) {
            int idx = u * 256 + t;
            int r   = idx >> 3;
            int j4  = idx & 7;
            int row = row0 + r;
            float4 x = make_float4(0.f, 0.f, 0.f, 0.f);
            if (row < N) x = *(const float4*)&X[row * 128 + kk + j4 * 4];
            __half2 h01 = __floats2half2_rn(x.x, x.y);
            __half2 h23 = __floats2half2_rn(x.z, x.w);
            uint2 o;
            o.x = *(unsigned*)&h01;
            o.y = *(unsigned*)&h23;
            *(uint2*)&xs[r * SXH + j4 * 4] = o;
        }
        // stage W chunk: pure copy of precomputed fp16 (uint4 = 8 halves)
#pragma unroll
        for (int u = 0; u < DOUT / 64; u++) {
            int idx = u * 256 + t;                 // BK*DOUT/8 slots
            int k   = idx / (DOUT / 8);
            int c8  = (idx % (DOUT / 8)) * 8;
            *(uint4*)&ws_h[k * SWH + c8] = *(const uint4*)&Wh[(kk + k) * DOUT + c8];
            *(uint4*)&ws_l[k * SWH + c8] = *(const uint4*)&Wl[(kk + k) * DOUT + c8];
        }
        __syncthreads();

#pragma unroll
        for (int ks = 0; ks < BK; ks += 16) {
            unsigned af[2][4];
#pragma unroll
            for (int mt = 0; mt < 2; mt++) {
                int r = rowW0 + mt * 16 + a_row;
                int c = ks + a_col;
                ldm_x4(sptr(&xs[r * SXH + c]), af[mt][0], af[mt][1], af[mt][2], af[mt][3]);
            }
            unsigned bh[2][4], bl[2][4];
#pragma unroll
            for (int np = 0; np < 2; np++) {
                int k = ks + b_row;
                int n = colW0 + np * 16 + b_col;
                ldm_x4t(sptr(&ws_h[k * SWH + n]), bh[np][0], bh[np][1], bh[np][2], bh[np][3]);
                ldm_x4t(sptr(&ws_l[k * SWH + n]), bl[np][0], bl[np][1], bl[np][2], bl[np][3]);
            }
#pragma unroll
            for (int mt = 0; mt < 2; mt++) {
#pragma unroll
                for (int nt = 0; nt < 4; nt++) {
                    int np = nt >> 1, hf = (nt & 1) * 2;
                    mma16816(acc[mt][nt], af[mt], bh[np][hf], bh[np][hf + 1]);
                    mma16816(acc[mt][nt], af[mt], bl[np][hf], bl[np][hf + 1]);
                }
            }
        }
        __syncthreads();
    }

    // epilogue: scale by dinv, convert fp16, store
#pragma unroll
    for (int mt = 0; mt < 2; mt++) {
#pragma unroll
        for (int nt = 0; nt < 4; nt++) {
            int col = colW0 + nt * 8 + (lane & 3) * 2;
            int r0  = row0 + rowW0 + mt * 16 + (lane >> 2);
            int r1  = r0 + 8;
            if (r0 < N) {
                float s = g_dinv[r0];
                __half2 h = __floats2half2_rn(acc[mt][nt][0] * s, acc[mt][nt][1] * s);
                *(unsigned*)&H[r0 * DOUT + col] = *(unsigned*)&h;
            }
            if (r1 < N) {
                float s = g_dinv[r1];
                __half2 h = __floats2half2_rn(acc[mt][nt][2] * s, acc[mt][nt][3] * s);
                *(unsigned*)&H[r1 * DOUT + col] = *(unsigned*)&h;
            }
        }
    }
}

// ---------------------------------------------------------------------------
// Aggregate per dst node: OUT[d] = dinv[d]*(HS[d] + sum_in HS[src]) + b (+relu)
// (exact R10 body)
// ---------------------------------------------------------------------------
template <int DOUT, bool RELU, int LAYER>
__global__ void k_agg(const float* __restrict__ bias,
                      float* __restrict__ outp, int N)
{
    constexpr int TPN = DOUT / 8;
    constexpr int NPB = 256 / TPN;

    const __half* HS  = (LAYER == 0) ? g_hs : g_hs2;
    float*        OUT = (LAYER == 0) ? g_x2 : outp;

    int t    = threadIdx.x;
    int node = blockIdx.x * NPB + t / TPN;
    int c8   = (t % TPN) * 8;
    if (node >= N) return;

    float a[8];
    {
        uint4 v = *(const uint4*)&HS[node * DOUT + c8];
        float2 f0 = __half22float2(*(__half2*)&v.x);
        float2 f1 = __half22float2(*(__half2*)&v.y);
        float2 f2 = __half22float2(*(__half2*)&v.z);
        float2 f3 = __half22float2(*(__half2*)&v.w);
        a[0] = f0.x; a[1] = f0.y; a[2] = f1.x; a[3] = f1.y;
        a[4] = f2.x; a[5] = f2.y; a[6] = f3.x; a[7] = f3.y;
    }

    int i = g_off[node];
    int e = g_off[node + 1];
    for (; i + 4 <= e; i += 4) {
        int s0 = g_csr_src[i + 0];
        int s1 = g_csr_src[i + 1];
        int s2 = g_csr_src[i + 2];
        int s3 = g_csr_src[i + 3];
        uint4 v0 = *(const uint4*)&HS[s0 * DOUT + c8];
        uint4 v1 = *(const uint4*)&HS[s1 * DOUT + c8];
        uint4 v2 = *(const uint4*)&HS[s2 * DOUT + c8];
        uint4 v3 = *(const uint4*)&HS[s3 * DOUT + c8];
#pragma unroll
        for (int q = 0; q < 4; q++) {
            unsigned w0 = (&v0.x)[q], w1 = (&v1.x)[q],
                     w2 = (&v2.x)[q], w3 = (&v3.x)[q];
            float2 f0 = __half22float2(*(__half2*)&w0);
            float2 f1 = __half22float2(*(__half2*)&w1);
            float2 f2 = __half22float2(*(__half2*)&w2);
            float2 f3 = __half22float2(*(__half2*)&w3);
            a[2 * q]     += f0.x + f1.x + f2.x + f3.x;
            a[2 * q + 1] += f0.y + f1.y + f2.y + f3.y;
        }
    }
    for (; i < e; i++) {
        int s0 = g_csr_src[i];
        uint4 v = *(const uint4*)&HS[s0 * DOUT + c8];
#pragma unroll
        for (int q = 0; q < 4; q++) {
            unsigned w0 = (&v.x)[q];
            float2 f = __half22float2(*(__half2*)&w0);
            a[2 * q]     += f.x;
            a[2 * q + 1] += f.y;
        }
    }

    float d = g_dinv[node];
    float r[8];
#pragma unroll
    for (int q = 0; q < 8; q++) {
        float o = a[q] * d + bias[c8 + q];
        if (RELU) o = fmaxf(o, 0.f);
        r[q] = o;
    }
    float4 ob0 = make_float4(r[0], r[1], r[2], r[3]);
    float4 ob1 = make_float4(r[4], r[5], r[6], r[7]);
    *(float4*)&OUT[node * DOUT + c8]     = ob0;
    *(float4*)&OUT[node * DOUT + c8 + 4] = ob1;
}

// ---------------------------------------------------------------------------
extern "C" void kernel_launch(void* const* d_in, const int* in_sizes, int n_in,
                              void* d_out, int out_size)
{
    const float* e_prev = (const float*)d_in[0];
    const int*   ei     = (const int*)d_in[1];
    const float* W1     = (const float*)d_in[2];
    const float* b1     = (const float*)d_in[3];
    const float* W2     = (const float*)d_in[4];
    const float* b2     = (const float*)d_in[5];
    float*       out    = (float*)d_out;

    int N = in_sizes[0] / 128;   // 50000
    int E = in_sizes[1] / 2;     // 800000

    // CSR build + W split (R10 ordering)
    k_init <<<(N + 255) / 256, 256>>>(ei, W1, W2, N);         // #1
    k_hist <<<(E / 4 + 255) / 256, 256>>>(ei, E, N);          // #2
    k_scan1<<<1, 1024>>>(N, E);                               // #3
    k_fill <<<(E / 4 + 255) / 256, 256>>>(ei, E, N);          // #4

    // Layer 1 (BM=64)
    k_gemm<128, 0><<<(N + 63) / 64, 256>>>(e_prev, N);        // #5
    {
        constexpr int NPB = 256 / (128 / 8);
        k_agg<128, true, 0><<<(N + NPB - 1) / NPB, 256>>>(b1, nullptr, N); // #6
    }

    // Layer 2 (BM=128)
    k_gemm<64, 1><<<(N + 127) / 128, 256>>>(nullptr, N);      // #7
    {
        constexpr int NPB = 256 / (64 / 8);
        k_agg<64, false, 1><<<(N + NPB - 1) / NPB, 256>>>(b2, out, N); // #8
    }
}